// round 6
// baseline (speedup 1.0000x reference)
#include <cuda_runtime.h>
#include <cub/cub.cuh>
#include <type_traits>

#define MAXN 1600000
#define MAXB 8
#define PRE_K 6000
#define POST_K 1000
#define MASKW 94            // ceil(6000/64)
#define NBINS 4096
#define CAP   6144          // per-image candidate buffer (= 1024 threads * 6 items)
#define NEGV  -1000000000.0f

// ---------------- static device scratch (no allocations allowed) ----------------
__device__ float4             g_boxes[MAXN];
__device__ float              g_score[MAXN];
__device__ unsigned int       g_hist[MAXB * NBINS];
__device__ int                g_thresh[MAXB];
__device__ unsigned int       g_cnt[MAXB];
__device__ unsigned long long g_buf[(size_t)MAXB * CAP];
__device__ float4             g_cboxes[MAXB * PRE_K];
__device__ int                g_cidx[MAXB * PRE_K];
__device__ int                g_rowany[MAXB * PRE_K];
__device__ unsigned long long g_mask[(size_t)MAXB * PRE_K * MASKW]; // upper-tri only; bss zero
__device__ int                g_kept[MAXB * POST_K];

// ---------------- XLA-exact sigmoid: 0.5 + 0.5*tanh(0.5x), fast-tanh poly ------
__device__ __forceinline__ float xla_tanh(float x) {
    float ax = fabsf(x);
    float xc = fminf(fmaxf(x, -7.99881172180175781f), 7.99881172180175781f);
    float x2 = __fmul_rn(xc, xc);
    float p = fmaf(x2, -2.76076847742355e-16f, 2.00018790482477e-13f);
    p = fmaf(p, x2, -8.60467152213735e-11f);
    p = fmaf(p, x2,  5.12229709037114e-08f);
    p = fmaf(p, x2,  1.48572235717979e-05f);
    p = fmaf(p, x2,  6.37261928875436e-04f);
    p = fmaf(p, x2,  4.89352455891786e-03f);
    float num = __fmul_rn(xc, p);
    float q = fmaf(x2, 1.19825839466702e-06f, 1.18534705686654e-04f);
    q = fmaf(q, x2, 2.26843463243900e-03f);
    q = fmaf(q, x2, 4.89352518554385e-03f);
    float r = __fdiv_rn(num, q);
    return (ax < 0.0004f) ? x : r;
}
__device__ __forceinline__ float xla_sigmoid(float x) {
    float t = xla_tanh(__fmul_rn(0.5f, x));
    return __fadd_rn(__fmul_rn(0.5f, t), 0.5f);
}

__device__ __forceinline__ int score_bin(float s) {
    if (s <= 0.0f) return 0;                       // NEGV and exact zeros -> bin 0
    int b = (int)(__fmul_rn(s, (float)NBINS));
    return b > (NBINS - 1) ? (NBINS - 1) : b;
}
__device__ __forceinline__ unsigned score_key(float s) {  // ascending uint <-> ascending float
    unsigned ub = __float_as_uint(s);
    return (ub & 0x80000000u) ? ~ub : (ub | 0x80000000u);
}

// ---------------- kernel 0: zero histogram -------------------------------------
__global__ void k_zero(int B)
{
    int t = blockIdx.x * blockDim.x + threadIdx.x;
    if (t < B * NBINS) g_hist[t] = 0;
}

// ---------------- kernel 1: decode boxes, score, histogram ---------------------
__global__ __launch_bounds__(256)
void k_decode(const float4* __restrict__ anchors, const int* __restrict__ bidx,
              const int* __restrict__ sizes, const float* __restrict__ logits,
              const float4* __restrict__ deltas, int N)
{
    int i = blockIdx.x * blockDim.x + threadIdx.x;
    if (i >= N) return;
    float4 a = anchors[i];
    float4 d = deltas[i];
    int b = bidx[i];
    float H = (float)sizes[2 * b];
    float W = (float)sizes[2 * b + 1];

    // exact op order of reference, no FMA contraction
    float aw = __fsub_rn(a.z, a.x);
    float ah = __fsub_rn(a.w, a.y);
    float ax = __fadd_rn(a.x, __fmul_rn(0.5f, aw));
    float ay = __fadd_rn(a.y, __fmul_rn(0.5f, ah));
    float px = __fadd_rn(ax, __fmul_rn(d.x, aw));
    float py = __fadd_rn(ay, __fmul_rn(d.y, ah));
    float twc = fminf(fmaxf(d.z, -10.0f), 10.0f);
    float thc = fminf(fmaxf(d.w, -10.0f), 10.0f);
    float pw = __fmul_rn(aw, expf(twc));   // expf == libdevice __nv_expf == XLA exp
    float ph = __fmul_rn(ah, expf(thc));
    float x1 = __fsub_rn(px, __fmul_rn(0.5f, pw));
    float y1 = __fsub_rn(py, __fmul_rn(0.5f, ph));
    float x2 = __fadd_rn(px, __fmul_rn(0.5f, pw));
    float y2 = __fadd_rn(py, __fmul_rn(0.5f, ph));
    float Wm1 = __fsub_rn(W, 1.0f);
    float Hm1 = __fsub_rn(H, 1.0f);
    x1 = fminf(fmaxf(x1, 0.0f), Wm1);
    y1 = fminf(fmaxf(y1, 0.0f), Hm1);
    x2 = fminf(fmaxf(x2, 0.0f), Wm1);
    y2 = fminf(fmaxf(y2, 0.0f), Hm1);
    bool valid = (__fsub_rn(x2, x1) >= 16.0f) && (__fsub_rn(y2, y1) >= 16.0f);

    float fg = xla_sigmoid(logits[i]);
    float sc = valid ? fg : NEGV;

    g_boxes[i] = make_float4(x1, y1, x2, y2);
    g_score[i] = sc;
    atomicAdd(&g_hist[b * NBINS + score_bin(sc)], 1u);
}

// ---------------- kernel 2: per-image threshold bin ----------------------------
__global__ __launch_bounds__(256)
void k_thresh()
{
    int b = blockIdx.x;
    int t = threadIdx.x;
    unsigned v[16]; unsigned s = 0;
    for (int k = 0; k < 16; k++) {
        v[k] = g_hist[b * NBINS + (NBINS - 1 - (t * 16 + k))];
        s += v[k];
    }
    __shared__ unsigned ps[256];
    ps[t] = s; __syncthreads();
    for (int off = 1; off < 256; off <<= 1) {
        unsigned x = (t >= off) ? ps[t - off] : 0u;
        __syncthreads();
        ps[t] += x;
        __syncthreads();
    }
    unsigned cum = ps[t] - s;        // exclusive prefix (descending order)
    for (int k = 0; k < 16; k++) {
        unsigned nc = cum + v[k];
        if (cum < PRE_K && nc >= PRE_K)
            g_thresh[b] = NBINS - 1 - (t * 16 + k);   // unique transition writer
        cum = nc;
    }
    if (t == 255 && cum < PRE_K) g_thresh[b] = 0;     // total < PRE_K: take all
    if (t == 0) g_cnt[b] = 0;
}

// ---------------- kernel 3: compact candidates (warp-aggregated atomics) -------
__global__ __launch_bounds__(256)
void k_compact(const int* __restrict__ bidx, int N)
{
    int i = blockIdx.x * blockDim.x + threadIdx.x;
    bool pass = false;
    int b = 0; float s = 0.0f;
    if (i < N) {
        b = bidx[i];
        s = g_score[i];
        pass = (score_bin(s) >= g_thresh[b]);
    }
    if (pass) {
        unsigned mask = __activemask();
        unsigned same = __match_any_sync(mask, b);
        int leader = __ffs(same) - 1;
        int lane = threadIdx.x & 31;
        unsigned pos = 0;
        if (lane == leader) pos = atomicAdd(&g_cnt[b], (unsigned)__popc(same));
        pos = __shfl_sync(mask, pos, leader);
        pos += __popc(same & ((1u << lane) - 1u));
        if (pos < CAP) {
            unsigned long long key =
                ((unsigned long long)(~score_key(s)) << 21) | (unsigned)i;
            g_buf[(size_t)b * CAP + pos] = key;
        }
    }
}

// ---------------- kernel 4: per-image block sort of candidates -----------------
// key = inv(scoreKey)<<21 | gidx : ascending sort == (score desc, idx asc)
using Sort6 = cub::BlockRadixSort<unsigned long long, 1024, 6, cub::NullType, 6>;
using Sort5 = cub::BlockRadixSort<unsigned long long, 1024, 6, cub::NullType, 5>;
using BlockSortT = std::conditional_t<(sizeof(Sort6::TempStorage) <= 200 * 1024),
                                      Sort6, Sort5>;
static_assert(sizeof(BlockSortT::TempStorage) <= 220 * 1024, "sort smem too big");

__global__ __launch_bounds__(1024)
void k_sortk()
{
    extern __shared__ char smem_raw[];
    BlockSortT::TempStorage& ts = *reinterpret_cast<BlockSortT::TempStorage*>(smem_raw);
    int b = blockIdx.x;
    unsigned cnt = g_cnt[b];
    if (cnt > CAP) cnt = CAP;
    unsigned long long keys[6];
    #pragma unroll
    for (int k = 0; k < 6; k++) {
        int p = threadIdx.x * 6 + k;
        keys[k] = (p < (int)cnt) ? g_buf[(size_t)b * CAP + p] : ~0ull;
    }
    BlockSortT(ts).Sort(keys, 0, 53);
    #pragma unroll
    for (int k = 0; k < 6; k++) {
        int p = threadIdx.x * 6 + k;
        if (p < PRE_K) {
            int o = b * PRE_K + p;
            g_rowany[o] = 0;
            unsigned long long key = keys[k];
            if (key >> 53) {             // padding sentinel
                g_cidx[o] = 0;
                g_cboxes[o] = make_float4(0, 0, 0, 0);
            } else {
                int gi = (int)(key & 0x1FFFFFu);
                g_cidx[o] = gi;
                g_cboxes[o] = g_boxes[gi];
            }
        }
    }
}

// ---------------- kernel 5: IoU suppression bitmask (upper triangle) -----------
// 256 rows per block vs 64 shared columns; div-free bound test with exact-div fallback
__global__ __launch_bounds__(256)
void k_mask()
{
    int b = blockIdx.z, rs = blockIdx.y, cb = blockIdx.x;
    if (cb < rs * 4) return;                 // whole 256-row stripe below diagonal
    __shared__ float4 sbx[64];
    __shared__ float  sar[64];
    int t = threadIdx.x;
    int cbase = cb * 64;
    int ncol = min(64, PRE_K - cbase);
    if (t < ncol) {
        float4 v = g_cboxes[b * PRE_K + cbase + t];
        sbx[t] = v;
        sar[t] = __fmul_rn(__fsub_rn(v.z, v.x), __fsub_rn(v.w, v.y));
    }
    __syncthreads();
    int i = rs * 256 + t;
    if (i >= PRE_K) return;
    int rg = i >> 6;
    if (cb < rg) return;                     // this row's word is lower triangle
    float4 bi_ = g_cboxes[b * PRE_K + i];
    float ai = __fmul_rn(__fsub_rn(bi_.z, bi_.x), __fsub_rn(bi_.w, bi_.y));
    unsigned long long bits = 0;
    #pragma unroll 2
    for (int j = 0; j < ncol; j++) {
        float4 bj = sbx[j];
        float ix1 = fmaxf(bi_.x, bj.x), iy1 = fmaxf(bi_.y, bj.y);
        float ix2 = fminf(bi_.z, bj.z), iy2 = fminf(bi_.w, bj.w);
        float inter = __fmul_rn(fmaxf(__fsub_rn(ix2, ix1), 0.0f),
                                fmaxf(__fsub_rn(iy2, iy1), 0.0f));
        float denom = __fadd_rn(__fsub_rn(__fadd_rn(sar[j], ai), inter), 1e-9f);
        float rhs  = 0.7f * denom;
        float diff = inter - rhs;
        bool sup;
        if (fabsf(diff) <= 1e-4f * rhs)      // borderline: exact reference math
            sup = __fdiv_rn(inter, denom) > 0.7f;
        else
            sup = diff > 0.0f;
        if (sup) bits |= 1ull << j;
    }
    g_mask[((size_t)b * PRE_K + i) * MASKW + cb] = bits;
    unsigned long long nonself = bits;
    if (cb == rg) nonself &= ~(1ull << (i - cbase));
    if (nonself) g_rowany[b * PRE_K + i] = 1;   // benign race: all writers store 1
}

// ---------------- kernel 6: greedy NMS, word-level scan (one warp per image) ---
__global__ __launch_bounds__(32)
void k_nms()
{
    int b = blockIdx.x;
    int lane = threadIdx.x;
    __shared__ unsigned long long srany[MASKW];
    __shared__ unsigned long long rem[MASKW];
    const int base = b * PRE_K;
    for (int w = lane; w < MASKW; w += 32) {
        unsigned long long bits = 0;
        int nrows = min(64, PRE_K - w * 64);
        for (int r = 0; r < nrows; r++)
            if (g_rowany[base + w * 64 + r]) bits |= 1ull << r;
        srany[w] = bits;
        rem[w] = 0ull;
    }
    unsigned cnt = g_cnt[b];
    int nvalid = (cnt > PRE_K) ? PRE_K : (int)cnt;
    __syncwarp();

    const unsigned long long* mrow = g_mask + (size_t)base * MASKW;
    const int outb = b * POST_K;
    int nk = 0;
    for (int w = 0; w * 64 < nvalid && nk < POST_K; w++) {
        int nb = nvalid - w * 64;
        unsigned long long validbits = (nb >= 64) ? ~0ull : ((1ull << nb) - 1ull);
        unsigned long long any = srany[w];
        unsigned long long cand = ~rem[w] & validbits;

        if (any == 0ull && cand == ~0ull && nk + 64 <= POST_K) {
            // fast path: full clean word, keep all 64
            g_kept[outb + nk + lane] = w * 64 + lane;
            g_kept[outb + nk + 32 + lane] = w * 64 + 32 + lane;
            nk += 64;
            continue;
        }
        // prefetch mask rows of potential suppressors in this word
        {
            unsigned long long s = cand & any;
            int np = 0;
            while (s && np < 4) {
                int j = __ffsll(s) - 1; s &= s - 1; np++;
                const unsigned long long* m = mrow + (size_t)(w * 64 + j) * MASKW;
                if (lane < 6)
                    asm volatile("prefetch.global.L2 [%0];" :: "l"(m + lane * 16));
            }
        }
        while (cand && nk < POST_K) {
            int j = __ffsll(cand) - 1;
            int i = w * 64 + j;
            if (lane == 0) g_kept[outb + nk] = i;
            nk++;
            unsigned long long above = (j < 63) ? (~0ull << (j + 1)) : 0ull;
            if ((any >> j) & 1ull) {
                // this kept row suppresses others: OR its mask into rem (words >= w only)
                const unsigned long long* m = mrow + (size_t)i * MASKW;
                for (int wi = w + lane; wi < MASKW; wi += 32) rem[wi] |= m[wi];
                __syncwarp();
                cand = cand & above & ~rem[w];
            } else {
                cand &= above;
            }
        }
    }
    for (int t = nk + lane; t < POST_K; t += 32) g_kept[outb + t] = -1;
}

// ---------------- kernel 7: write outputs --------------------------------------
__global__ __launch_bounds__(256)
void k_out(const float* __restrict__ logits, const float4* __restrict__ deltas,
           float* __restrict__ out, int B)
{
    int t = blockIdx.x * blockDim.x + threadIdx.x;
    int P = B * POST_K;
    if (t >= P) return;
    int b = t / POST_K;
    int j = g_kept[t];
    float4 pb = make_float4(0, 0, 0, 0), dl = make_float4(0, 0, 0, 0);
    float ob = 0.0f, bi = -1.0f, okf = 0.0f;
    if (j >= 0) {
        int gi = g_cidx[b * PRE_K + j];
        pb = g_cboxes[b * PRE_K + j];
        ob = logits[gi];
        dl = deltas[gi];
        bi = (float)b;
        okf = 1.0f;
    }
    // layout: props[4P] | bidx[P] | obj[P] | deltas[4P] | keep_ok[P]
    ((float4*)out)[t] = pb;
    out[4 * P + t] = bi;
    out[5 * P + t] = ob;
    ((float4*)(out + 6 * P))[t] = dl;
    out[10 * P + t] = okf;
}

// ---------------- launcher ------------------------------------------------------
extern "C" void kernel_launch(void* const* d_in, const int* in_sizes, int n_in,
                              void* d_out, int out_size)
{
    const float4* anchors = (const float4*)d_in[0];
    const int*    bidx    = (const int*)d_in[1];
    const int*    sizes   = (const int*)d_in[2];
    const float*  logits  = (const float*)d_in[3];
    const float4* deltas  = (const float4*)d_in[4];
    float* out = (float*)d_out;

    int N = in_sizes[0] / 4;
    int B = in_sizes[2] / 2;
    if (N > MAXN) N = MAXN;
    if (B > MAXB) B = MAXB;

    cudaFuncSetAttribute(k_sortk, cudaFuncAttributeMaxDynamicSharedMemorySize,
                         (int)sizeof(BlockSortT::TempStorage));

    k_zero<<<(B * NBINS + 255) / 256, 256>>>(B);
    k_decode<<<(N + 255) / 256, 256>>>(anchors, bidx, sizes, logits, deltas, N);
    k_thresh<<<B, 256>>>();
    k_compact<<<(N + 255) / 256, 256>>>(bidx, N);
    k_sortk<<<B, 1024, sizeof(BlockSortT::TempStorage)>>>();
    dim3 mg(MASKW, (PRE_K + 255) / 256, B);
    k_mask<<<mg, 256>>>();
    k_nms<<<B, 32>>>();
    k_out<<<(B * POST_K + 255) / 256, 256>>>(logits, deltas, out, B);
}

// round 7
// speedup vs baseline: 1.7167x; 1.7167x over previous
#include <cuda_runtime.h>
#include <cub/cub.cuh>

#define MAXN 1600000
#define MAXB 8
#define PRE_K 6000
#define POST_K 1000
#define MASKW 94            // ceil(6000/64)
#define C1 2048             // phase-1 NMS window
#define MASKW1 32           // C1/64
#define NBINS 4096
#define CAPA 3072           // buffer A (top ~2048), sorted by 1024x3
#define CAPB 4096           // buffer B (ranks ~2048..6029), sorted by 1024x4
#define NEGV  -1000000000.0f

// ---------------- static device scratch (no allocations allowed) ----------------
__device__ float4             g_boxes[MAXN];
__device__ float              g_score[MAXN];
__device__ unsigned int       g_hist[MAXB * NBINS];
__device__ int                g_t[MAXB];      // threshold bin for top PRE_K
__device__ int                g_t2[MAXB];     // threshold bin for top ~C1
__device__ unsigned int       g_cntA[MAXB];
__device__ unsigned int       g_cntB[MAXB];
__device__ unsigned long long g_bufA[(size_t)MAXB * CAPA];
__device__ unsigned long long g_bufB[(size_t)MAXB * CAPB];
__device__ float4             g_cboxes[MAXB * PRE_K];
__device__ int                g_cidx[MAXB * PRE_K];
__device__ int                g_rowany[MAXB * PRE_K];
__device__ unsigned long long g_mask[(size_t)MAXB * MASKW * PRE_K]; // TRANSPOSED [b][cb][row]
__device__ int                g_kept[MAXB * POST_K];
__device__ int                g_done[MAXB];

// ---------------- XLA-exact sigmoid: 0.5 + 0.5*tanh(0.5x), fast-tanh poly ------
__device__ __forceinline__ float xla_tanh(float x) {
    float ax = fabsf(x);
    float xc = fminf(fmaxf(x, -7.99881172180175781f), 7.99881172180175781f);
    float x2 = __fmul_rn(xc, xc);
    float p = fmaf(x2, -2.76076847742355e-16f, 2.00018790482477e-13f);
    p = fmaf(p, x2, -8.60467152213735e-11f);
    p = fmaf(p, x2,  5.12229709037114e-08f);
    p = fmaf(p, x2,  1.48572235717979e-05f);
    p = fmaf(p, x2,  6.37261928875436e-04f);
    p = fmaf(p, x2,  4.89352455891786e-03f);
    float num = __fmul_rn(xc, p);
    float q = fmaf(x2, 1.19825839466702e-06f, 1.18534705686654e-04f);
    q = fmaf(q, x2, 2.26843463243900e-03f);
    q = fmaf(q, x2, 4.89352518554385e-03f);
    float r = __fdiv_rn(num, q);
    return (ax < 0.0004f) ? x : r;
}
__device__ __forceinline__ float xla_sigmoid(float x) {
    float t = xla_tanh(__fmul_rn(0.5f, x));
    return __fadd_rn(__fmul_rn(0.5f, t), 0.5f);
}

__device__ __forceinline__ int score_bin(float s) {
    if (s <= 0.0f) return 0;
    int b = (int)(__fmul_rn(s, (float)NBINS));
    return b > (NBINS - 1) ? (NBINS - 1) : b;
}
__device__ __forceinline__ unsigned score_key(float s) {
    unsigned ub = __float_as_uint(s);
    return (ub & 0x80000000u) ? ~ub : (ub | 0x80000000u);
}
__device__ __forceinline__ unsigned long long mask_word(int b, int wi, int row) {
    return g_mask[((size_t)b * MASKW + wi) * PRE_K + row];
}

// ---------------- kernel 0: zero histogram -------------------------------------
__global__ void k_zero(int B)
{
    int t = blockIdx.x * blockDim.x + threadIdx.x;
    if (t < B * NBINS) g_hist[t] = 0;
}

// ---------------- kernel 1: decode boxes, score, histogram ---------------------
__global__ __launch_bounds__(256)
void k_decode(const float4* __restrict__ anchors, const int* __restrict__ bidx,
              const int* __restrict__ sizes, const float* __restrict__ logits,
              const float4* __restrict__ deltas, int N)
{
    int i = blockIdx.x * blockDim.x + threadIdx.x;
    if (i >= N) return;
    float4 a = anchors[i];
    float4 d = deltas[i];
    int b = bidx[i];
    float H = (float)sizes[2 * b];
    float W = (float)sizes[2 * b + 1];

    float aw = __fsub_rn(a.z, a.x);
    float ah = __fsub_rn(a.w, a.y);
    float ax = __fadd_rn(a.x, __fmul_rn(0.5f, aw));
    float ay = __fadd_rn(a.y, __fmul_rn(0.5f, ah));
    float px = __fadd_rn(ax, __fmul_rn(d.x, aw));
    float py = __fadd_rn(ay, __fmul_rn(d.y, ah));
    float twc = fminf(fmaxf(d.z, -10.0f), 10.0f);
    float thc = fminf(fmaxf(d.w, -10.0f), 10.0f);
    float pw = __fmul_rn(aw, expf(twc));
    float ph = __fmul_rn(ah, expf(thc));
    float x1 = __fsub_rn(px, __fmul_rn(0.5f, pw));
    float y1 = __fsub_rn(py, __fmul_rn(0.5f, ph));
    float x2 = __fadd_rn(px, __fmul_rn(0.5f, pw));
    float y2 = __fadd_rn(py, __fmul_rn(0.5f, ph));
    float Wm1 = __fsub_rn(W, 1.0f);
    float Hm1 = __fsub_rn(H, 1.0f);
    x1 = fminf(fmaxf(x1, 0.0f), Wm1);
    y1 = fminf(fmaxf(y1, 0.0f), Hm1);
    x2 = fminf(fmaxf(x2, 0.0f), Wm1);
    y2 = fminf(fmaxf(y2, 0.0f), Hm1);
    bool valid = (__fsub_rn(x2, x1) >= 16.0f) && (__fsub_rn(y2, y1) >= 16.0f);

    float fg = xla_sigmoid(logits[i]);
    float sc = valid ? fg : NEGV;

    g_boxes[i] = make_float4(x1, y1, x2, y2);
    g_score[i] = sc;
    atomicAdd(&g_hist[b * NBINS + score_bin(sc)], 1u);
}

// ---------------- kernel 2: thresholds + clear candidate arrays ----------------
__global__ __launch_bounds__(256)
void k_thresh()
{
    int b = blockIdx.x;
    int t = threadIdx.x;

    // clear per-candidate state (deterministic padding for unwritten slots)
    for (int i = t; i < PRE_K; i += 256) {
        g_rowany[b * PRE_K + i] = 0;
        g_cidx[b * PRE_K + i] = 0;
        g_cboxes[b * PRE_K + i] = make_float4(0, 0, 0, 0);
    }

    unsigned v[16]; unsigned s = 0;
    for (int k = 0; k < 16; k++) {
        v[k] = g_hist[b * NBINS + (NBINS - 1 - (t * 16 + k))];
        s += v[k];
    }
    __shared__ unsigned ps[256];
    __shared__ int s_t, s_t2;
    if (t == 0) { s_t = 1; s_t2 = 1; }
    ps[t] = s; __syncthreads();
    for (int off = 1; off < 256; off <<= 1) {
        unsigned x = (t >= off) ? ps[t - off] : 0u;
        __syncthreads();
        ps[t] += x;
        __syncthreads();
    }
    unsigned cum = ps[t] - s;        // exclusive prefix (descending bins)
    for (int k = 0; k < 16; k++) {
        unsigned nc = cum + v[k];
        int bin = NBINS - 1 - (t * 16 + k);
        if (cum < C1    && nc >= C1)    s_t2 = bin;
        if (cum < PRE_K && nc >= PRE_K) s_t  = bin;
        cum = nc;
    }
    __syncthreads();
    if (t == 0) {
        int tt = s_t, tt2 = s_t2;
        if (tt < 1) tt = 1;
        if (tt2 <= tt) tt2 = tt + 1;   // keep A strictly above B; A may undershoot C1 (handled)
        g_t[b] = tt; g_t2[b] = tt2;
        g_cntA[b] = 0; g_cntB[b] = 0;
        g_done[b] = 0;
    }
}

// ---------------- kernel 3: compact candidates into A/B buffers ----------------
__global__ __launch_bounds__(256)
void k_compact(const int* __restrict__ bidx, int N)
{
    int i = blockIdx.x * blockDim.x + threadIdx.x;
    if (i >= N) return;
    int b = bidx[i];
    float s = g_score[i];
    int bin = score_bin(s);
    if (bin < g_t[b]) return;
    bool toA = (bin >= g_t2[b]);
    unsigned long long key = ((unsigned long long)(~score_key(s)) << 21) | (unsigned)i;

    unsigned mask = __activemask();
    unsigned same = __match_any_sync(mask, b * 2 + (toA ? 1 : 0));
    int leader = __ffs(same) - 1;
    int lane = threadIdx.x & 31;
    unsigned pos = 0;
    unsigned* ctr = toA ? &g_cntA[b] : &g_cntB[b];
    if (lane == leader) pos = atomicAdd(ctr, (unsigned)__popc(same));
    pos = __shfl_sync(mask, pos, leader);
    pos += __popc(same & ((1u << lane) - 1u));
    if (toA) { if (pos < CAPA) g_bufA[(size_t)b * CAPA + pos] = key; }
    else     { if (pos < CAPB) g_bufB[(size_t)b * CAPB + pos] = key; }
}

// ---------------- kernel 4: per-image block sorts (A and B concurrently) -------
using SortA = cub::BlockRadixSort<unsigned long long, 1024, 3>;
using SortB = cub::BlockRadixSort<unsigned long long, 1024, 4>;

__global__ __launch_bounds__(1024)
void k_sort()
{
    extern __shared__ char smem_raw[];
    int b = blockIdx.y;
    if (blockIdx.x == 0) {
        SortA::TempStorage& ts = *reinterpret_cast<SortA::TempStorage*>(smem_raw);
        unsigned cnt = g_cntA[b]; if (cnt > CAPA) cnt = CAPA;
        unsigned long long keys[3];
        #pragma unroll
        for (int k = 0; k < 3; k++) {
            int p = threadIdx.x * 3 + k;
            keys[k] = (p < (int)cnt) ? g_bufA[(size_t)b * CAPA + p] : ~0ull;
        }
        SortA(ts).Sort(keys, 0, 53);
        #pragma unroll
        for (int k = 0; k < 3; k++) {
            int p = threadIdx.x * 3 + k;
            if (p < (int)cnt) {
                int gi = (int)(keys[k] & 0x1FFFFFu);
                g_cidx[b * PRE_K + p] = gi;
                g_cboxes[b * PRE_K + p] = g_boxes[gi];
            }
        }
    } else {
        SortB::TempStorage& ts = *reinterpret_cast<SortB::TempStorage*>(smem_raw);
        unsigned cA = g_cntA[b]; if (cA > CAPA) cA = CAPA;
        unsigned cnt = g_cntB[b]; if (cnt > CAPB) cnt = CAPB;
        unsigned long long keys[4];
        #pragma unroll
        for (int k = 0; k < 4; k++) {
            int p = threadIdx.x * 4 + k;
            keys[k] = (p < (int)cnt) ? g_bufB[(size_t)b * CAPB + p] : ~0ull;
        }
        SortB(ts).Sort(keys, 0, 53);
        #pragma unroll
        for (int k = 0; k < 4; k++) {
            int p = threadIdx.x * 4 + k;
            int o = (int)cA + p;
            if (p < (int)cnt && o < PRE_K) {
                int gi = (int)(keys[k] & 0x1FFFFFu);
                g_cidx[b * PRE_K + o] = gi;
                g_cboxes[b * PRE_K + o] = g_boxes[gi];
            }
        }
    }
}

// ---------------- kernel 5: IoU suppression bitmask (transposed store) ---------
// PHASE2=false: rows/cols < C1 only. PHASE2=true: remainder, skipped when done.
template<bool PHASE2>
__global__ __launch_bounds__(256)
void k_mask_t()
{
    int b = blockIdx.z, rs = blockIdx.y, cb = blockIdx.x;
    if (PHASE2) {
        if (g_done[b]) return;
        if (rs < C1 / 256 && cb < MASKW1) return;   // phase-1 already covered
    }
    if (cb < rs * 4) return;                         // stripe fully below diagonal
    __shared__ float4 sbx[64];
    __shared__ float  sar[64];
    int t = threadIdx.x;
    int cbase = cb * 64;
    int ncol = min(64, PRE_K - cbase);
    if (t < ncol) {
        float4 v = g_cboxes[b * PRE_K + cbase + t];
        sbx[t] = v;
        sar[t] = __fmul_rn(__fsub_rn(v.z, v.x), __fsub_rn(v.w, v.y));
    }
    __syncthreads();
    int i = rs * 256 + t;
    if (i >= PRE_K) return;
    int rg = i >> 6;
    if (cb < rg) return;
    float4 bi_ = g_cboxes[b * PRE_K + i];
    float ai = __fmul_rn(__fsub_rn(bi_.z, bi_.x), __fsub_rn(bi_.w, bi_.y));
    unsigned long long bits = 0;
    #pragma unroll 2
    for (int j = 0; j < ncol; j++) {
        float4 bj = sbx[j];
        float ix1 = fmaxf(bi_.x, bj.x), iy1 = fmaxf(bi_.y, bj.y);
        float ix2 = fminf(bi_.z, bj.z), iy2 = fminf(bi_.w, bj.w);
        float inter = __fmul_rn(fmaxf(__fsub_rn(ix2, ix1), 0.0f),
                                fmaxf(__fsub_rn(iy2, iy1), 0.0f));
        float denom = __fadd_rn(__fsub_rn(__fadd_rn(sar[j], ai), inter), 1e-9f);
        float rhs  = 0.7f * denom;
        float diff = inter - rhs;
        bool sup;
        if (fabsf(diff) <= 1e-4f * rhs)      // borderline: exact reference math
            sup = __fdiv_rn(inter, denom) > 0.7f;
        else
            sup = diff > 0.0f;
        if (sup) bits |= 1ull << j;
    }
    g_mask[((size_t)b * MASKW + cb) * PRE_K + i] = bits;   // coalesced over i
    unsigned long long nonself = bits;
    if (cb == rg) nonself &= ~(1ull << (i - cbase));
    if (nonself) g_rowany[b * PRE_K + i] = 1;
}

// ---------------- kernel 6a: phase-1 NMS over first C1 candidates --------------
__global__ __launch_bounds__(32)
void k_nms1()
{
    int b = blockIdx.x;
    int lane = threadIdx.x;
    unsigned cA = g_cntA[b]; if (cA > CAPA) cA = CAPA;
    unsigned cB = g_cntB[b]; if (cB > CAPB) cB = CAPB;
    int nvalid = min((int)(cA + cB), PRE_K);
    int nscan = min(min((int)cA, C1), nvalid);

    __shared__ unsigned long long srany[MASKW1];
    __shared__ unsigned long long rem[MASKW1];
    const int base = b * PRE_K;
    for (int w = lane; w < MASKW1; w += 32) {
        unsigned long long bits = 0;
        int nrows = min(64, nscan - w * 64);
        for (int r = 0; r < nrows; r++)
            if (g_rowany[base + w * 64 + r]) bits |= 1ull << r;
        srany[w] = bits;
        rem[w] = 0ull;
    }
    __syncwarp();

    const int outb = b * POST_K;
    int nk = 0;
    for (int w = 0; w * 64 < nscan && nk < POST_K; w++) {
        int nb = nscan - w * 64;
        unsigned long long validbits = (nb >= 64) ? ~0ull : ((1ull << nb) - 1ull);
        unsigned long long any = srany[w];
        unsigned long long cand = ~rem[w] & validbits;

        if (any == 0ull && cand == ~0ull && nk + 64 <= POST_K) {
            g_kept[outb + nk + lane] = w * 64 + lane;
            g_kept[outb + nk + 32 + lane] = w * 64 + 32 + lane;
            nk += 64;
            continue;
        }
        while (cand && nk < POST_K) {
            int j = __ffsll(cand) - 1;
            int i = w * 64 + j;
            if (lane == 0) g_kept[outb + nk] = i;
            nk++;
            unsigned long long above = (j < 63) ? (~0ull << (j + 1)) : 0ull;
            if ((any >> j) & 1ull) {
                for (int wi = w + lane; wi < MASKW1; wi += 32)
                    rem[wi] |= mask_word(b, wi, i);
                __syncwarp();
                cand = cand & above & ~rem[w];
            } else {
                cand &= above;
            }
        }
    }
    int done = (nk >= POST_K) || (nscan >= nvalid);
    if (lane == 0) g_done[b] = done;
    for (int t = nk + lane; t < POST_K; t += 32) g_kept[outb + t] = -1;
}

// ---------------- kernel 6b: full NMS fallback (skipped when done) -------------
__global__ __launch_bounds__(32)
void k_nms2()
{
    int b = blockIdx.x;
    if (g_done[b]) return;
    int lane = threadIdx.x;
    unsigned cA = g_cntA[b]; if (cA > CAPA) cA = CAPA;
    unsigned cB = g_cntB[b]; if (cB > CAPB) cB = CAPB;
    int nvalid = min((int)(cA + cB), PRE_K);

    __shared__ unsigned long long srany[MASKW];
    __shared__ unsigned long long rem[MASKW];
    const int base = b * PRE_K;
    for (int w = lane; w < MASKW; w += 32) {
        unsigned long long bits = 0;
        int nrows = min(64, min(PRE_K, nvalid) - w * 64);
        for (int r = 0; r < nrows; r++)
            if (g_rowany[base + w * 64 + r]) bits |= 1ull << r;
        srany[w] = bits;
        rem[w] = 0ull;
    }
    __syncwarp();

    const int outb = b * POST_K;
    int nk = 0;
    for (int w = 0; w * 64 < nvalid && nk < POST_K; w++) {
        int nb = nvalid - w * 64;
        unsigned long long validbits = (nb >= 64) ? ~0ull : ((1ull << nb) - 1ull);
        unsigned long long any = srany[w];
        unsigned long long cand = ~rem[w] & validbits;

        if (any == 0ull && cand == ~0ull && nk + 64 <= POST_K) {
            g_kept[outb + nk + lane] = w * 64 + lane;
            g_kept[outb + nk + 32 + lane] = w * 64 + 32 + lane;
            nk += 64;
            continue;
        }
        while (cand && nk < POST_K) {
            int j = __ffsll(cand) - 1;
            int i = w * 64 + j;
            if (lane == 0) g_kept[outb + nk] = i;
            nk++;
            unsigned long long above = (j < 63) ? (~0ull << (j + 1)) : 0ull;
            if ((any >> j) & 1ull) {
                for (int wi = w + lane; wi < MASKW; wi += 32)
                    rem[wi] |= mask_word(b, wi, i);
                __syncwarp();
                cand = cand & above & ~rem[w];
            } else {
                cand &= above;
            }
        }
    }
    for (int t = nk + lane; t < POST_K; t += 32) g_kept[outb + t] = -1;
}

// ---------------- kernel 7: write outputs --------------------------------------
__global__ __launch_bounds__(256)
void k_out(const float* __restrict__ logits, const float4* __restrict__ deltas,
           float* __restrict__ out, int B)
{
    int t = blockIdx.x * blockDim.x + threadIdx.x;
    int P = B * POST_K;
    if (t >= P) return;
    int b = t / POST_K;
    int j = g_kept[t];
    float4 pb = make_float4(0, 0, 0, 0), dl = make_float4(0, 0, 0, 0);
    float ob = 0.0f, bi = -1.0f, okf = 0.0f;
    if (j >= 0) {
        int gi = g_cidx[b * PRE_K + j];
        pb = g_cboxes[b * PRE_K + j];
        ob = logits[gi];
        dl = deltas[gi];
        bi = (float)b;
        okf = 1.0f;
    }
    ((float4*)out)[t] = pb;
    out[4 * P + t] = bi;
    out[5 * P + t] = ob;
    ((float4*)(out + 6 * P))[t] = dl;
    out[10 * P + t] = okf;
}

// ---------------- launcher ------------------------------------------------------
extern "C" void kernel_launch(void* const* d_in, const int* in_sizes, int n_in,
                              void* d_out, int out_size)
{
    const float4* anchors = (const float4*)d_in[0];
    const int*    bidx    = (const int*)d_in[1];
    const int*    sizes   = (const int*)d_in[2];
    const float*  logits  = (const float*)d_in[3];
    const float4* deltas  = (const float4*)d_in[4];
    float* out = (float*)d_out;

    int N = in_sizes[0] / 4;
    int B = in_sizes[2] / 2;
    if (N > MAXN) N = MAXN;
    if (B > MAXB) B = MAXB;

    size_t smA = sizeof(SortA::TempStorage), smB = sizeof(SortB::TempStorage);
    int smem = (int)(smA > smB ? smA : smB);
    cudaFuncSetAttribute(k_sort, cudaFuncAttributeMaxDynamicSharedMemorySize, smem);

    k_zero<<<(B * NBINS + 255) / 256, 256>>>(B);
    k_decode<<<(N + 255) / 256, 256>>>(anchors, bidx, sizes, logits, deltas, N);
    k_thresh<<<B, 256>>>();
    k_compact<<<(N + 255) / 256, 256>>>(bidx, N);
    k_sort<<<dim3(2, B, 1), 1024, smem>>>();
    k_mask_t<false><<<dim3(MASKW1, C1 / 256, B), 256>>>();
    k_nms1<<<B, 32>>>();
    k_mask_t<true><<<dim3(MASKW, (PRE_K + 255) / 256, B), 256>>>();
    k_nms2<<<B, 32>>>();
    k_out<<<(B * POST_K + 255) / 256, 256>>>(logits, deltas, out, B);
}

// round 8
// speedup vs baseline: 3.5228x; 2.0521x over previous
#include <cuda_runtime.h>

#define MAXN 1600000
#define MAXB 8
#define PRE_K 6000
#define POST_K 1000
#define MASKW 94            // ceil(6000/64)
#define C1 2048             // phase-1 NMS window
#define MASKW1 32           // C1/64
#define NBINS 4096
#define CAPA 3072           // buffer A (top ~2048)
#define CAPB 4096           // buffer B (ranks ~2048..6030)
#define SORTN 4096          // bitonic sort size (>= CAPA, >= CAPB)
#define NEGV  -1000000000.0f

// ---------------- static device scratch (no allocations allowed) ----------------
__device__ float4             g_boxes[MAXN];
__device__ float              g_score[MAXN];
__device__ unsigned int       g_hist[MAXB * NBINS];
__device__ int                g_t[MAXB];      // threshold bin for top PRE_K
__device__ int                g_t2[MAXB];     // threshold bin for top ~C1
__device__ unsigned int       g_cntA[MAXB];
__device__ unsigned int       g_cntB[MAXB];
__device__ unsigned long long g_bufA[(size_t)MAXB * CAPA];
__device__ unsigned long long g_bufB[(size_t)MAXB * CAPB];
__device__ float4             g_cboxes[MAXB * PRE_K];
__device__ int                g_cidx[MAXB * PRE_K];
__device__ int                g_rowany[MAXB * PRE_K];
__device__ unsigned long long g_mask[(size_t)MAXB * MASKW * PRE_K]; // TRANSPOSED [b][cb][row]
__device__ int                g_kept[MAXB * POST_K];
__device__ int                g_done[MAXB];

// ---------------- XLA-exact sigmoid: 0.5 + 0.5*tanh(0.5x), fast-tanh poly ------
__device__ __forceinline__ float xla_tanh(float x) {
    float ax = fabsf(x);
    float xc = fminf(fmaxf(x, -7.99881172180175781f), 7.99881172180175781f);
    float x2 = __fmul_rn(xc, xc);
    float p = fmaf(x2, -2.76076847742355e-16f, 2.00018790482477e-13f);
    p = fmaf(p, x2, -8.60467152213735e-11f);
    p = fmaf(p, x2,  5.12229709037114e-08f);
    p = fmaf(p, x2,  1.48572235717979e-05f);
    p = fmaf(p, x2,  6.37261928875436e-04f);
    p = fmaf(p, x2,  4.89352455891786e-03f);
    float num = __fmul_rn(xc, p);
    float q = fmaf(x2, 1.19825839466702e-06f, 1.18534705686654e-04f);
    q = fmaf(q, x2, 2.26843463243900e-03f);
    q = fmaf(q, x2, 4.89352518554385e-03f);
    float r = __fdiv_rn(num, q);
    return (ax < 0.0004f) ? x : r;
}
__device__ __forceinline__ float xla_sigmoid(float x) {
    float t = xla_tanh(__fmul_rn(0.5f, x));
    return __fadd_rn(__fmul_rn(0.5f, t), 0.5f);
}

__device__ __forceinline__ int score_bin(float s) {
    if (s <= 0.0f) return 0;
    int b = (int)(__fmul_rn(s, (float)NBINS));
    return b > (NBINS - 1) ? (NBINS - 1) : b;
}
__device__ __forceinline__ unsigned score_key(float s) {
    unsigned ub = __float_as_uint(s);
    return (ub & 0x80000000u) ? ~ub : (ub | 0x80000000u);
}
__device__ __forceinline__ unsigned long long mask_word(int b, int wi, int row) {
    return g_mask[((size_t)b * MASKW + wi) * PRE_K + row];
}

// ---------------- bitonic sort of SORTN u64 keys in shared memory --------------
__device__ __forceinline__ void bitonic_sort_smem(unsigned long long* sk)
{
    #pragma unroll 1
    for (int k = 2; k <= SORTN; k <<= 1) {
        #pragma unroll 1
        for (int j = k >> 1; j > 0; j >>= 1) {
            #pragma unroll
            for (int it = 0; it < SORTN / 2 / 1024; it++) {
                int t = threadIdx.x + it * 1024;
                int i = ((t & ~(j - 1)) << 1) | (t & (j - 1));
                int p = i + j;
                bool up = ((i & k) == 0);
                unsigned long long a = sk[i], c = sk[p];
                if ((a > c) == up) { sk[i] = c; sk[p] = a; }
            }
            __syncthreads();
        }
    }
}

// ---------------- kernel 0: zero histogram -------------------------------------
__global__ void k_zero(int B)
{
    int t = blockIdx.x * blockDim.x + threadIdx.x;
    if (t < B * NBINS) g_hist[t] = 0;
}

// ---------------- kernel 1: decode boxes, score, histogram ---------------------
__global__ __launch_bounds__(256)
void k_decode(const float4* __restrict__ anchors, const int* __restrict__ bidx,
              const int* __restrict__ sizes, const float* __restrict__ logits,
              const float4* __restrict__ deltas, int N)
{
    int i = blockIdx.x * blockDim.x + threadIdx.x;
    if (i >= N) return;
    float4 a = anchors[i];
    float4 d = deltas[i];
    int b = bidx[i];
    float H = (float)sizes[2 * b];
    float W = (float)sizes[2 * b + 1];

    float aw = __fsub_rn(a.z, a.x);
    float ah = __fsub_rn(a.w, a.y);
    float ax = __fadd_rn(a.x, __fmul_rn(0.5f, aw));
    float ay = __fadd_rn(a.y, __fmul_rn(0.5f, ah));
    float px = __fadd_rn(ax, __fmul_rn(d.x, aw));
    float py = __fadd_rn(ay, __fmul_rn(d.y, ah));
    float twc = fminf(fmaxf(d.z, -10.0f), 10.0f);
    float thc = fminf(fmaxf(d.w, -10.0f), 10.0f);
    float pw = __fmul_rn(aw, expf(twc));
    float ph = __fmul_rn(ah, expf(thc));
    float x1 = __fsub_rn(px, __fmul_rn(0.5f, pw));
    float y1 = __fsub_rn(py, __fmul_rn(0.5f, ph));
    float x2 = __fadd_rn(px, __fmul_rn(0.5f, pw));
    float y2 = __fadd_rn(py, __fmul_rn(0.5f, ph));
    float Wm1 = __fsub_rn(W, 1.0f);
    float Hm1 = __fsub_rn(H, 1.0f);
    x1 = fminf(fmaxf(x1, 0.0f), Wm1);
    y1 = fminf(fmaxf(y1, 0.0f), Hm1);
    x2 = fminf(fmaxf(x2, 0.0f), Wm1);
    y2 = fminf(fmaxf(y2, 0.0f), Hm1);
    bool valid = (__fsub_rn(x2, x1) >= 16.0f) && (__fsub_rn(y2, y1) >= 16.0f);

    float fg = xla_sigmoid(logits[i]);
    float sc = valid ? fg : NEGV;

    g_boxes[i] = make_float4(x1, y1, x2, y2);
    g_score[i] = sc;
    // bin 0 is never consulted by the threshold logic (g_t >= 1) — skip the
    // atomic for invalid boxes to avoid same-address REDG serialization.
    if (sc > 0.0f)
        atomicAdd(&g_hist[b * NBINS + score_bin(sc)], 1u);
}

// ---------------- kernel 2: thresholds + clear candidate arrays ----------------
__global__ __launch_bounds__(256)
void k_thresh()
{
    int b = blockIdx.x;
    int t = threadIdx.x;

    // clear per-candidate state (deterministic padding for unwritten slots)
    for (int i = t; i < PRE_K; i += 256) {
        g_rowany[b * PRE_K + i] = 0;
        g_cidx[b * PRE_K + i] = 0;
        g_cboxes[b * PRE_K + i] = make_float4(0, 0, 0, 0);
    }

    unsigned v[16]; unsigned s = 0;
    for (int k = 0; k < 16; k++) {
        v[k] = g_hist[b * NBINS + (NBINS - 1 - (t * 16 + k))];
        s += v[k];
    }
    __shared__ unsigned ps[256];
    __shared__ int s_t, s_t2;
    if (t == 0) { s_t = 1; s_t2 = 1; }
    ps[t] = s; __syncthreads();
    for (int off = 1; off < 256; off <<= 1) {
        unsigned x = (t >= off) ? ps[t - off] : 0u;
        __syncthreads();
        ps[t] += x;
        __syncthreads();
    }
    unsigned cum = ps[t] - s;        // exclusive prefix (descending bins)
    for (int k = 0; k < 16; k++) {
        unsigned nc = cum + v[k];
        int bin = NBINS - 1 - (t * 16 + k);
        if (cum < C1    && nc >= C1)    s_t2 = bin;
        if (cum < PRE_K && nc >= PRE_K) s_t  = bin;
        cum = nc;
    }
    __syncthreads();
    if (t == 0) {
        int tt = s_t, tt2 = s_t2;
        if (tt < 1) tt = 1;
        if (tt2 <= tt) tt2 = tt + 1;   // keep A strictly above B
        g_t[b] = tt; g_t2[b] = tt2;
        g_cntA[b] = 0; g_cntB[b] = 0;
        g_done[b] = 0;
    }
}

// ---------------- kernel 3: compact candidates into A/B buffers ----------------
__global__ __launch_bounds__(256)
void k_compact(const int* __restrict__ bidx, int N)
{
    int i = blockIdx.x * blockDim.x + threadIdx.x;
    if (i >= N) return;
    int b = bidx[i];
    float s = g_score[i];
    int bin = score_bin(s);
    if (bin < g_t[b]) return;
    bool toA = (bin >= g_t2[b]);
    unsigned long long key = ((unsigned long long)(~score_key(s)) << 21) | (unsigned)i;

    unsigned mask = __activemask();
    unsigned same = __match_any_sync(mask, b * 2 + (toA ? 1 : 0));
    int leader = __ffs(same) - 1;
    int lane = threadIdx.x & 31;
    unsigned pos = 0;
    unsigned* ctr = toA ? &g_cntA[b] : &g_cntB[b];
    if (lane == leader) pos = atomicAdd(ctr, (unsigned)__popc(same));
    pos = __shfl_sync(mask, pos, leader);
    pos += __popc(same & ((1u << lane) - 1u));
    if (toA) { if (pos < CAPA) g_bufA[(size_t)b * CAPA + pos] = key; }
    else     { if (pos < CAPB) g_bufB[(size_t)b * CAPB + pos] = key; }
}

// ---------------- kernel 4a: bitonic sort of A (critical path) -----------------
__global__ __launch_bounds__(1024)
void k_sortA()
{
    __shared__ unsigned long long sk[SORTN];
    int b = blockIdx.x;
    unsigned cnt = g_cntA[b]; if (cnt > CAPA) cnt = CAPA;
    for (int p = threadIdx.x; p < SORTN; p += 1024)
        sk[p] = (p < (int)cnt) ? g_bufA[(size_t)b * CAPA + p] : ~0ull;
    __syncthreads();
    bitonic_sort_smem(sk);
    for (int p = threadIdx.x; p < (int)cnt; p += 1024) {
        int gi = (int)(sk[p] & 0x1FFFFFu);
        g_cidx[b * PRE_K + p] = gi;
        g_cboxes[b * PRE_K + p] = g_boxes[gi];
    }
}

// ---------------- kernel 4b: bitonic sort of B (fallback only) -----------------
__global__ __launch_bounds__(1024)
void k_sortB()
{
    int b = blockIdx.x;
    if (g_done[b]) return;
    __shared__ unsigned long long sk[SORTN];
    unsigned cA = g_cntA[b]; if (cA > CAPA) cA = CAPA;
    unsigned cnt = g_cntB[b]; if (cnt > CAPB) cnt = CAPB;
    for (int p = threadIdx.x; p < SORTN; p += 1024)
        sk[p] = (p < (int)cnt) ? g_bufB[(size_t)b * CAPB + p] : ~0ull;
    __syncthreads();
    bitonic_sort_smem(sk);
    for (int p = threadIdx.x; p < (int)cnt; p += 1024) {
        int o = (int)cA + p;
        if (o < PRE_K) {
            int gi = (int)(sk[p] & 0x1FFFFFu);
            g_cidx[b * PRE_K + o] = gi;
            g_cboxes[b * PRE_K + o] = g_boxes[gi];
        }
    }
}

// ---------------- kernel 5: IoU suppression bitmask (transposed store) ---------
// PHASE2=false: rows/cols < C1 only. PHASE2=true: remainder, skipped when done.
template<bool PHASE2>
__global__ __launch_bounds__(256)
void k_mask_t()
{
    int b = blockIdx.z, rs = blockIdx.y, cb = blockIdx.x;
    if (PHASE2) {
        if (g_done[b]) return;
        if (rs < C1 / 256 && cb < MASKW1) return;   // phase-1 already covered
    }
    if (cb < rs * 4) return;                         // stripe fully below diagonal
    __shared__ float4 sbx[64];
    __shared__ float  sar[64];
    int t = threadIdx.x;
    int cbase = cb * 64;
    int ncol = min(64, PRE_K - cbase);
    if (t < ncol) {
        float4 v = g_cboxes[b * PRE_K + cbase + t];
        sbx[t] = v;
        sar[t] = __fmul_rn(__fsub_rn(v.z, v.x), __fsub_rn(v.w, v.y));
    }
    __syncthreads();
    int i = rs * 256 + t;
    if (i >= PRE_K) return;
    int rg = i >> 6;
    if (cb < rg) return;
    float4 bi_ = g_cboxes[b * PRE_K + i];
    float ai = __fmul_rn(__fsub_rn(bi_.z, bi_.x), __fsub_rn(bi_.w, bi_.y));
    unsigned long long bits = 0;
    #pragma unroll 2
    for (int j = 0; j < ncol; j++) {
        float4 bj = sbx[j];
        float ix1 = fmaxf(bi_.x, bj.x), iy1 = fmaxf(bi_.y, bj.y);
        float ix2 = fminf(bi_.z, bj.z), iy2 = fminf(bi_.w, bj.w);
        float inter = __fmul_rn(fmaxf(__fsub_rn(ix2, ix1), 0.0f),
                                fmaxf(__fsub_rn(iy2, iy1), 0.0f));
        float denom = __fadd_rn(__fsub_rn(__fadd_rn(sar[j], ai), inter), 1e-9f);
        float rhs  = 0.7f * denom;
        float diff = inter - rhs;
        bool sup;
        if (fabsf(diff) <= 1e-4f * rhs)      // borderline: exact reference math
            sup = __fdiv_rn(inter, denom) > 0.7f;
        else
            sup = diff > 0.0f;
        if (sup) bits |= 1ull << j;
    }
    g_mask[((size_t)b * MASKW + cb) * PRE_K + i] = bits;   // coalesced over i
    unsigned long long nonself = bits;
    if (cb == rg) nonself &= ~(1ull << (i - cbase));
    if (nonself) g_rowany[b * PRE_K + i] = 1;
}

// ---------------- kernel 6a: phase-1 NMS over first C1 candidates --------------
__global__ __launch_bounds__(32)
void k_nms1()
{
    int b = blockIdx.x;
    int lane = threadIdx.x;
    unsigned cA = g_cntA[b]; if (cA > CAPA) cA = CAPA;
    unsigned cB = g_cntB[b]; if (cB > CAPB) cB = CAPB;
    int nvalid = min((int)(cA + cB), PRE_K);
    int nscan = min(min((int)cA, C1), nvalid);

    __shared__ unsigned long long srany[MASKW1];
    __shared__ unsigned long long rem[MASKW1];
    const int base = b * PRE_K;
    for (int w = lane; w < MASKW1; w += 32) {
        unsigned long long bits = 0;
        int nrows = min(64, nscan - w * 64);
        for (int r = 0; r < nrows; r++)
            if (g_rowany[base + w * 64 + r]) bits |= 1ull << r;
        srany[w] = bits;
        rem[w] = 0ull;
    }
    __syncwarp();

    const int outb = b * POST_K;
    int nk = 0;
    for (int w = 0; w * 64 < nscan && nk < POST_K; w++) {
        int nb = nscan - w * 64;
        unsigned long long validbits = (nb >= 64) ? ~0ull : ((1ull << nb) - 1ull);
        unsigned long long any = srany[w];
        unsigned long long cand = ~rem[w] & validbits;

        if (any == 0ull && cand == ~0ull && nk + 64 <= POST_K) {
            g_kept[outb + nk + lane] = w * 64 + lane;
            g_kept[outb + nk + 32 + lane] = w * 64 + 32 + lane;
            nk += 64;
            continue;
        }
        while (cand && nk < POST_K) {
            int j = __ffsll(cand) - 1;
            int i = w * 64 + j;
            if (lane == 0) g_kept[outb + nk] = i;
            nk++;
            unsigned long long above = (j < 63) ? (~0ull << (j + 1)) : 0ull;
            if ((any >> j) & 1ull) {
                for (int wi = w + lane; wi < MASKW1; wi += 32)
                    rem[wi] |= mask_word(b, wi, i);
                __syncwarp();
                cand = cand & above & ~rem[w];
            } else {
                cand &= above;
            }
        }
    }
    int done = (nk >= POST_K) || (nscan >= nvalid);
    if (lane == 0) g_done[b] = done;
    for (int t = nk + lane; t < POST_K; t += 32) g_kept[outb + t] = -1;
}

// ---------------- kernel 6b: full NMS fallback (skipped when done) -------------
__global__ __launch_bounds__(32)
void k_nms2()
{
    int b = blockIdx.x;
    if (g_done[b]) return;
    int lane = threadIdx.x;
    unsigned cA = g_cntA[b]; if (cA > CAPA) cA = CAPA;
    unsigned cB = g_cntB[b]; if (cB > CAPB) cB = CAPB;
    int nvalid = min((int)(cA + cB), PRE_K);

    __shared__ unsigned long long srany[MASKW];
    __shared__ unsigned long long rem[MASKW];
    const int base = b * PRE_K;
    for (int w = lane; w < MASKW; w += 32) {
        unsigned long long bits = 0;
        int nrows = min(64, min(PRE_K, nvalid) - w * 64);
        for (int r = 0; r < nrows; r++)
            if (g_rowany[base + w * 64 + r]) bits |= 1ull << r;
        srany[w] = bits;
        rem[w] = 0ull;
    }
    __syncwarp();

    const int outb = b * POST_K;
    int nk = 0;
    for (int w = 0; w * 64 < nvalid && nk < POST_K; w++) {
        int nb = nvalid - w * 64;
        unsigned long long validbits = (nb >= 64) ? ~0ull : ((1ull << nb) - 1ull);
        unsigned long long any = srany[w];
        unsigned long long cand = ~rem[w] & validbits;

        if (any == 0ull && cand == ~0ull && nk + 64 <= POST_K) {
            g_kept[outb + nk + lane] = w * 64 + lane;
            g_kept[outb + nk + 32 + lane] = w * 64 + 32 + lane;
            nk += 64;
            continue;
        }
        while (cand && nk < POST_K) {
            int j = __ffsll(cand) - 1;
            int i = w * 64 + j;
            if (lane == 0) g_kept[outb + nk] = i;
            nk++;
            unsigned long long above = (j < 63) ? (~0ull << (j + 1)) : 0ull;
            if ((any >> j) & 1ull) {
                for (int wi = w + lane; wi < MASKW; wi += 32)
                    rem[wi] |= mask_word(b, wi, i);
                __syncwarp();
                cand = cand & above & ~rem[w];
            } else {
                cand &= above;
            }
        }
    }
    for (int t = nk + lane; t < POST_K; t += 32) g_kept[outb + t] = -1;
}

// ---------------- kernel 7: write outputs --------------------------------------
__global__ __launch_bounds__(256)
void k_out(const float* __restrict__ logits, const float4* __restrict__ deltas,
           float* __restrict__ out, int B)
{
    int t = blockIdx.x * blockDim.x + threadIdx.x;
    int P = B * POST_K;
    if (t >= P) return;
    int b = t / POST_K;
    int j = g_kept[t];
    float4 pb = make_float4(0, 0, 0, 0), dl = make_float4(0, 0, 0, 0);
    float ob = 0.0f, bi = -1.0f, okf = 0.0f;
    if (j >= 0) {
        int gi = g_cidx[b * PRE_K + j];
        pb = g_cboxes[b * PRE_K + j];
        ob = logits[gi];
        dl = deltas[gi];
        bi = (float)b;
        okf = 1.0f;
    }
    ((float4*)out)[t] = pb;
    out[4 * P + t] = bi;
    out[5 * P + t] = ob;
    ((float4*)(out + 6 * P))[t] = dl;
    out[10 * P + t] = okf;
}

// ---------------- launcher ------------------------------------------------------
extern "C" void kernel_launch(void* const* d_in, const int* in_sizes, int n_in,
                              void* d_out, int out_size)
{
    const float4* anchors = (const float4*)d_in[0];
    const int*    bidx    = (const int*)d_in[1];
    const int*    sizes   = (const int*)d_in[2];
    const float*  logits  = (const float*)d_in[3];
    const float4* deltas  = (const float4*)d_in[4];
    float* out = (float*)d_out;

    int N = in_sizes[0] / 4;
    int B = in_sizes[2] / 2;
    if (N > MAXN) N = MAXN;
    if (B > MAXB) B = MAXB;

    k_zero<<<(B * NBINS + 255) / 256, 256>>>(B);
    k_decode<<<(N + 255) / 256, 256>>>(anchors, bidx, sizes, logits, deltas, N);
    k_thresh<<<B, 256>>>();
    k_compact<<<(N + 255) / 256, 256>>>(bidx, N);
    k_sortA<<<B, 1024>>>();
    k_mask_t<false><<<dim3(MASKW1, C1 / 256, B), 256>>>();
    k_nms1<<<B, 32>>>();
    k_sortB<<<B, 1024>>>();
    k_mask_t<true><<<dim3(MASKW, (PRE_K + 255) / 256, B), 256>>>();
    k_nms2<<<B, 32>>>();
    k_out<<<(B * POST_K + 255) / 256, 256>>>(logits, deltas, out, B);
}